// round 12
// baseline (speedup 1.0000x reference)
#include <cuda_runtime.h>

#define IN 448
#define OUT 224
#define NP 512          // 8*64 planes
#define TY 56           // tile height (224 = 4*56)
#define FULLM 0xffffffffu

__device__ __forceinline__ int refl(int i) {
    i = (i < 0) ? -i : i;
    return (i >= IN) ? (2 * IN - 2 - i) : i;
}

__device__ __forceinline__ float fmax4(float a, float b, float c, float d) {
    return fmaxf(fmaxf(a, b), fmaxf(c, d));
}

__device__ __forceinline__ float2 vmax2(float2 a, float2 b) {
    return make_float2(fmaxf(a.x, b.x), fmaxf(a.y, b.y));
}

// ---------------------------------------------------------------------------
// S2 (4x4 windows) from base, single-pass 3 rows/warp (32 warps cover 96 rows);
// overshoot rows land in pad rows (never read). Write guard on DEST pitch.
// ---------------------------------------------------------------------------
template <int SRCP, int DSTP>
__device__ __forceinline__ void build_s2_slide(const float* __restrict__ src,
                                               float* __restrict__ dst,
                                               int w, int l, int lo, int hi) {
    const int j0 = min(2 * l, SRCP - 2);
    const bool on = (2 * l + 2 <= DSTP);
    const int i0 = lo + 3 * w;
    if (i0 <= hi) {                          // warp-uniform
        const float* s = src + i0 * SRCP + j0;
        float2 r[6];
        #pragma unroll
        for (int k = 0; k < 6; k++)
            r[k] = *reinterpret_cast<const float2*>(s + k * SRCP);
        float2 t12 = vmax2(r[1], r[2]);
        float2 t34 = vmax2(r[3], r[4]);
        float2 o[3];
        o[0] = vmax2(vmax2(r[0], t12), r[3]);
        o[1] = vmax2(t12, t34);
        o[2] = vmax2(vmax2(r[2], t34), r[5]);
        float* d = dst + i0 * DSTP + 2 * l;
        #pragma unroll
        for (int k = 0; k < 3; k++) {
            float mx = o[k].x, my = o[k].y;
            float nx  = __shfl_down_sync(FULLM, mx, 1);
            float ny  = __shfl_down_sync(FULLM, my, 1);
            float mmx = __shfl_down_sync(FULLM, mx, 2);
            if (on)
                *reinterpret_cast<float2*>(d + k * DSTP) =
                    make_float2(fmax4(mx, my, nx, ny), fmax4(my, nx, ny, mmx));
        }
    }
}

// S3 from S2 (vertical span 4), single-pass 3 rows/warp.
template <int SRCP, int DSTP>
__device__ __forceinline__ void build_s4(const float* __restrict__ src,
                                         float* __restrict__ dst,
                                         int w, int l, int lo, int hi) {
    const int j0 = min(2 * l, SRCP - 2);
    const bool on = (2 * l + 2 <= DSTP);
    const int i0 = lo + 3 * w;
    if (i0 <= hi) {                          // warp-uniform
        const float* s = src + i0 * SRCP + j0;
        float* d = dst + i0 * DSTP + 2 * l;
        #pragma unroll
        for (int k = 0; k < 3; k++) {
            float2 a = *reinterpret_cast<const float2*>(s + k * SRCP);
            float2 b = *reinterpret_cast<const float2*>(s + (k + 4) * SRCP);
            float mx = fmaxf(a.x, b.x);
            float my = fmaxf(a.y, b.y);
            float bx = __shfl_down_sync(FULLM, mx, 2);
            float by = __shfl_down_sync(FULLM, my, 2);
            if (on)
                *reinterpret_cast<float2*>(d + k * DSTP) =
                    make_float2(fmaxf(mx, bx), fmaxf(my, by));
        }
    }
}

// ---------------------------------------------------------------------------
// Dynamic smem layout (floats), T=56 tile, pad rows absorb overshoot:
//  sEE  @ 0     : 72 x 46 = 3312  (valid rows 0..69)
//  sS2E @ 3312  : 69 x 44 = 3036  (valid rows 0..66, col 43 pad)
//  sS3E @ 6348  : 65 x 40 = 2600  (valid rows 0..62, col 39 pad)
//  sOO  @ 8948  : 68 x 42 = 2856  (valid rows 0..65)
//  sS2O @ 11804 : 65 x 40 = 2600  (valid rows 0..62, col 39 pad)
//  sS3O @ 14404 : 61 x 36 = 2196  (valid rows 0..58, col 35 pad)
//  total 16600 floats = 66400 B -> 2 blocks/SM @ 1024 thr = 2048 threads
// ---------------------------------------------------------------------------
#define SMEM_FLOATS 16600
#define SMEM_BYTES  (SMEM_FLOATS * 4)

__global__ __launch_bounds__(1024, 2) void fused_pool(const float* __restrict__ x,
                                                      float* __restrict__ out) {
    extern __shared__ __align__(16) float sm[];
    float* sEE  = sm;
    float* sS2E = sm + 3312;
    float* sS3E = sm + 6348;
    float* sOO  = sm + 8948;
    float* sS2O = sm + 11804;
    float* sS3O = sm + 14404;

    const int p   = blockIdx.z;
    const int ty0 = blockIdx.y * TY;
    const int tx0 = blockIdx.x * 32;
    const int tid = threadIdx.x;
    const int w   = tid >> 5;    // warp 0..31
    const int l   = tid & 31;

    // Column extremes of |dx| over this tile (block-uniform)
    int dxl = tx0 - 112, dxh = tx0 + 31 - 112;
    int dxmin = (dxl > 0) ? dxl : ((dxh < 0) ? -dxh : 0);
    int dxmax = max(abs(dxl), abs(dxh));
    int dxmin2 = dxmin * dxmin, dxmax2 = dxmax * dxmax;

    // Per-zone row ranges over 56 rows: two ballots per zone -> 64-bit mask
    int l2 = 127, h2 = -1, l8 = 127, h8 = -1, l14 = 127, h14 = -1;
    int l20 = 127, h20 = -1, l26 = 127, h26 = -1;
    {
        int dyA = ty0 + l - 112;          // rows 0..31
        int dyB = dyA + 32;               // rows 32..63 (use l<24)
        int rmA = dyA * dyA + dxmin2, rMA = dyA * dyA + dxmax2;
        int rmB = dyB * dyB + dxmin2, rMB = dyB * dyB + dxmax2;
        bool okB = (l < 24);
        unsigned mA, mB;
        unsigned long long M;
        #define ZRANGE(cA, cB, LO, HI) \
            mA = __ballot_sync(FULLM, (cA)); \
            mB = __ballot_sync(FULLM, okB && (cB)); \
            M = mA | ((unsigned long long)mB << 32); \
            if (M) { LO = __ffsll((long long)M) - 1; HI = 63 - __clzll((long long)M); }
        ZRANGE(rmA < 3600,                  rmB < 3600,                  l2,  h2);
        ZRANGE(rmA < 5625  && rMA >= 3600,  rmB < 5625  && rMB >= 3600,  l8,  h8);
        ZRANGE(rmA < 8100  && rMA >= 5625,  rmB < 8100  && rMB >= 5625,  l14, h14);
        ZRANGE(rmA < 11025 && rMA >= 8100,  rmB < 11025 && rMB >= 8100,  l20, h20);
        ZRANGE(rMA >= 11025,                rMB >= 11025,                l26, h26);
        #undef ZRANGE
    }

    // Producer row ranges from consumer needs (caps for T=56)
    int s3eLo = 127, s3eHi = -1;
    if (h26 >= 0) { s3eLo = l26 + 1; s3eHi = h26 + 6; }
    int s2eLo = 127, s2eHi = -1;
    if (h14 >= 0) { s2eLo = l14 + 4; s2eHi = h14 + 7; }
    if (s3eHi >= 0) { s2eLo = min(s2eLo, s3eLo); s2eHi = max(s2eHi, s3eHi + 4); }
    s2eHi = min(s2eHi, 66);
    int eeLo = 127, eeHi = -1;
    if (h2 >= 0) { eeLo = l2 + 7; eeHi = h2 + 7; }
    if (s2eHi >= 0) { eeLo = min(eeLo, s2eLo); eeHi = max(eeHi, s2eHi + 3); }
    eeHi = min(eeHi, 69);
    s3eHi = min(s3eHi, 62);

    int s3oLo = 127, s3oHi = -1;
    if (h20 >= 0) { s3oLo = l20; s3oHi = h20 + 2; }
    int s2oLo = 127, s2oHi = -1;
    if (h8 >= 0) { s2oLo = l8 + 3; s2oHi = h8 + 3; }
    if (s3oHi >= 0) { s2oLo = min(s2oLo, s3oLo); s2oHi = max(s2oHi, s3oHi + 4); }
    s2oHi = min(s2oHi, 62);
    int ooLo = 127, ooHi = -1;
    if (s2oHi >= 0) { ooLo = s2oLo; ooHi = min(s2oHi + 3, 65); }
    s3oHi = min(s3oHi, 58);

    const float* in = x + p * (IN * IN);
    const float NEG_INF = __int_as_float(0xff800000);
    const bool xInt = (tx0 >= 32) && (tx0 <= 160);
    const bool yInt = (ty0 >= TY) && (ty0 <= 2 * TY);  // ty0 in {56,112}

    if (xInt && yInt) {
        // ========== INTERIOR FAST PATH (no reflection; R9-style staging) ====
        {
            const int i0 = eeLo + 3 * w;
            if (i0 <= eeHi) {                              // warp-uniform
                const int cb = 2 * tx0 - 16 + 4 * l;       // 16B-aligned
                const float* P = in + (2 * (ty0 - 7 + i0)) * IN + cb;
                float* d = sEE + i0 * 46 + 2 * l;
                #pragma unroll
                for (int k = 0; k < 3; k++) {
                    float4 A = *reinterpret_cast<const float4*>(P + (2 * k) * IN);
                    float4 B = *reinterpret_cast<const float4*>(P + (2 * k + 1) * IN);
                    float mzw = fmax4(A.z, A.w, B.z, B.w);
                    float mxy = fmax4(A.x, A.y, B.x, B.y);
                    float v1 = __shfl_down_sync(FULLM, mxy, 1);
                    if (l < 23)
                        *reinterpret_cast<float2*>(d + k * 46) =
                            make_float2(mzw, v1);
                }
            }
        }
        {
            const int i0 = ooLo + 3 * w;
            if (i0 <= ooHi) {                              // warp-uniform
                const int cb = 2 * tx0 - 12 + 4 * l;       // 16B-aligned
                const float* P = in + (2 * (ty0 - 5 + i0) + 1) * IN + cb;
                float* d = sOO + i0 * 42 + 2 * l;
                #pragma unroll
                for (int k = 0; k < 3; k++) {
                    float4 A = *reinterpret_cast<const float4*>(P + (2 * k) * IN);
                    float4 B = *reinterpret_cast<const float4*>(P + (2 * k + 1) * IN);
                    float mw  = fmaxf(A.w, B.w);
                    float mx  = fmaxf(A.x, B.x);
                    float dyz = fmax4(A.y, A.z, B.y, B.z);
                    float nx = __shfl_down_sync(FULLM, mx, 1);
                    float nd = __shfl_down_sync(FULLM, dyz, 1);
                    if (l < 21)
                        *reinterpret_cast<float2*>(d + k * 42) =
                            make_float2(fmaxf(mw, nx), nd);
                }
            }
        }
    } else {
        // ================= GENERAL PATH (border tiles) =====================
        if (xInt) {
            const int cb = 2 * tx0 - 16 + 4 * l;
            for (int i = eeLo + w; i <= eeHi; i += 32) {
                int yp = ty0 - 7 + i;
                int r0, r1;
                if ((unsigned)yp < 224u) { r0 = 2 * yp; r1 = 2 * yp + 1; }
                else                     { r0 = refl(2 * yp); r1 = refl(2 * yp + 1); }
                float4 A = *reinterpret_cast<const float4*>(in + r0 * IN + cb);
                float4 B = *reinterpret_cast<const float4*>(in + r1 * IN + cb);
                float mzw = fmax4(A.z, A.w, B.z, B.w);
                float mxy = fmax4(A.x, A.y, B.x, B.y);
                float v1 = __shfl_down_sync(FULLM, mxy, 1);
                if (l < 23)
                    *reinterpret_cast<float2*>(sEE + i * 46 + 2 * l) =
                        make_float2(mzw, v1);
            }
        } else if (l < 23) {
            const int j0 = 2 * l;
            for (int i = eeLo + w; i <= eeHi; i += 32) {
                int yp = ty0 - 7 + i;
                int r0, r1;
                if ((unsigned)yp < 224u) { r0 = 2 * yp; r1 = 2 * yp + 1; }
                else                     { r0 = refl(2 * yp); r1 = refl(2 * yp + 1); }
                const float* R0 = in + r0 * IN;
                const float* R1 = in + r1 * IN;
                int xp0 = tx0 - 7 + j0;
                float v0, v1;
                if ((unsigned)xp0 < 223u) {
                    float2 a = *reinterpret_cast<const float2*>(R0 + 2 * xp0);
                    float2 b = *reinterpret_cast<const float2*>(R0 + 2 * xp0 + 2);
                    float2 c = *reinterpret_cast<const float2*>(R1 + 2 * xp0);
                    float2 d = *reinterpret_cast<const float2*>(R1 + 2 * xp0 + 2);
                    v0 = fmax4(a.x, a.y, c.x, c.y);
                    v1 = fmax4(b.x, b.y, d.x, d.y);
                } else {
                    int c0 = refl(2 * xp0),     c1 = refl(2 * xp0 + 1);
                    v0 = fmax4(R0[c0], R0[c1], R1[c0], R1[c1]);
                    int c2 = refl(2 * xp0 + 2), c3 = refl(2 * xp0 + 3);
                    v1 = fmax4(R0[c2], R0[c3], R1[c2], R1[c3]);
                }
                *reinterpret_cast<float2*>(sEE + i * 46 + j0) = make_float2(v0, v1);
            }
        }

        if (xInt) {
            const int cb = 2 * tx0 - 12 + 4 * l;
            for (int i = ooLo + w; i <= ooHi; i += 32) {
                int gy = ty0 - 5 + i;
                float v0 = NEG_INF, v1 = NEG_INF;
                if ((unsigned)gy < 224u) {        // warp-uniform
                    int r0 = 2 * gy + 1;
                    int r1 = (gy == 223) ? 446 : 2 * gy + 2;
                    float4 A = *reinterpret_cast<const float4*>(in + r0 * IN + cb);
                    float4 B = *reinterpret_cast<const float4*>(in + r1 * IN + cb);
                    float mw  = fmaxf(A.w, B.w);
                    float mx  = fmaxf(A.x, B.x);
                    float dyz = fmax4(A.y, A.z, B.y, B.z);
                    float nx = __shfl_down_sync(FULLM, mx, 1);
                    float nd = __shfl_down_sync(FULLM, dyz, 1);
                    v0 = fmaxf(mw, nx);
                    v1 = nd;
                }
                if (l < 21)
                    *reinterpret_cast<float2*>(sOO + i * 42 + 2 * l) =
                        make_float2(v0, v1);
            }
        } else if (l < 21) {
            const int j0 = 2 * l;
            for (int i = ooLo + w; i <= ooHi; i += 32) {
                int gy = ty0 - 5 + i;
                float v0 = NEG_INF, v1 = NEG_INF;
                if ((unsigned)gy < 224u) {
                    int r0 = 2 * gy + 1;
                    int r1 = (gy == 223) ? 446 : 2 * gy + 2;
                    const float* R0 = in + r0 * IN;
                    const float* R1 = in + r1 * IN;
                    int gx0 = tx0 - 5 + j0;
                    if ((unsigned)gx0 < 224u) {
                        int c0 = 2 * gx0 + 1;
                        int c1 = (gx0 == 223) ? 446 : 2 * gx0 + 2;
                        v0 = fmax4(R0[c0], R0[c1], R1[c0], R1[c1]);
                    }
                    int gx1 = gx0 + 1;
                    if ((unsigned)gx1 < 224u) {
                        int c0 = 2 * gx1 + 1;
                        int c1 = (gx1 == 223) ? 446 : 2 * gx1 + 2;
                        v1 = fmax4(R0[c0], R0[c1], R1[c0], R1[c1]);
                    }
                }
                *reinterpret_cast<float2*>(sOO + i * 42 + j0) = make_float2(v0, v1);
            }
        }
    }
    __syncthreads();

    // ---- Level-2 tables (4x4 windows)
    build_s2_slide<46, 44>(sEE, sS2E, w, l, s2eLo, s2eHi);
    build_s2_slide<42, 40>(sOO, sS2O, w, l, s2oLo, s2oHi);
    __syncthreads();

    // ---- Level-3 tables (8x8 windows)
    build_s4<44, 40>(sS2E, sS3E, w, l, s3eLo, s3eHi);
    build_s4<40, 36>(sS2O, sS3O, w, l, s3oLo, s3oHi);
    __syncthreads();

    // ---- Queries: up to 2 output pixels per thread (rows w and w+32)
    #pragma unroll
    for (int q = 0; q < 2; q++) {
        int ry = w + q * 32;
        if (ry < TY) {                      // warp-uniform
            int rx = l;
            int oy = ty0 + ry, ox = tx0 + rx;
            int dy = oy - 112, dx = ox - 112;
            int d2 = dy * dy + dx * dx;
            float v;
            if (d2 < 3600) {
                v = sEE[(ry + 7) * 46 + (rx + 7)];                   // k=2
            } else if (d2 < 5625) {
                v = sS2O[(ry + 3) * 40 + (rx + 3)];                  // k=8
            } else if (d2 < 8100) {
                const float* b = sS2E + (ry + 4) * 44 + (rx + 4);    // k=14
                v = fmax4(b[0], b[3], b[3 * 44], b[3 * 44 + 3]);
            } else if (d2 < 11025) {
                const float* b = sS3O + ry * 36 + rx;                // k=20
                v = fmax4(b[0], b[2], b[2 * 36], b[2 * 36 + 2]);
            } else {
                const float* b = sS3E + (ry + 1) * 40 + (rx + 1);    // k=26
                v = fmax4(b[0], b[5], b[5 * 40], b[5 * 40 + 5]);
            }
            out[(p * OUT + oy) * OUT + ox] = v;
        }
    }
}

extern "C" void kernel_launch(void* const* d_in, const int* in_sizes, int n_in,
                              void* d_out, int out_size) {
    const float* x = (const float*)d_in[0];
    float* out = (float*)d_out;
    cudaFuncSetAttribute(fused_pool, cudaFuncAttributeMaxDynamicSharedMemorySize,
                         SMEM_BYTES);
    fused_pool<<<dim3(7, 4, NP), 1024, SMEM_BYTES>>>(x, out);
}

// round 13
// speedup vs baseline: 1.1914x; 1.1914x over previous
#include <cuda_runtime.h>

#define IN 448
#define OUT 224
#define NP 512          // 8*64 planes
#define FULLM 0xffffffffu

__device__ __forceinline__ int refl(int i) {
    i = (i < 0) ? -i : i;
    return (i >= IN) ? (2 * IN - 2 - i) : i;
}

__device__ __forceinline__ float fmax4(float a, float b, float c, float d) {
    return fmaxf(fmaxf(a, b), fmaxf(c, d));
}

__device__ __forceinline__ float2 vmax2(float2 a, float2 b) {
    return make_float2(fmaxf(a.x, b.x), fmaxf(a.y, b.y));
}

// ---------------------------------------------------------------------------
// S2 (4x4 windows) from base: 8 warps per pipeline, 6 output rows per warp
// via a running 4-row vertical window (9 row-reads / 6 outputs). Overshoot
// writes (<= hi+5) land in pad rows; overshoot reads (<= hi+8) stay inside
// the (enlarged) source allocation. Store guard on DEST pitch.
// ---------------------------------------------------------------------------
template <int SRCP, int DSTP>
__device__ __forceinline__ void build_s2_run(const float* __restrict__ src,
                                             float* __restrict__ dst,
                                             int wsub, int l, int lo, int hi) {
    const int j0 = min(2 * l, SRCP - 2);
    const bool on = (2 * l + 2 <= DSTP);
    const int i0 = lo + 6 * wsub;
    if (i0 <= hi) {                          // warp-uniform
        const float* s = src + i0 * SRCP + j0;
        float* d = dst + i0 * DSTP + 2 * l;
        float2 r0 = *reinterpret_cast<const float2*>(s);
        float2 r1 = *reinterpret_cast<const float2*>(s + SRCP);
        float2 r2 = *reinterpret_cast<const float2*>(s + 2 * SRCP);
        #pragma unroll
        for (int k = 0; k < 6; k++) {
            float2 r3 = *reinterpret_cast<const float2*>(s + (k + 3) * SRCP);
            float2 o = vmax2(vmax2(r0, r1), vmax2(r2, r3));
            float mx = o.x, my = o.y;
            float nx  = __shfl_down_sync(FULLM, mx, 1);
            float ny  = __shfl_down_sync(FULLM, my, 1);
            float mmx = __shfl_down_sync(FULLM, mx, 2);
            if (on)
                *reinterpret_cast<float2*>(d + k * DSTP) =
                    make_float2(fmax4(mx, my, nx, ny), fmax4(my, nx, ny, mmx));
            r0 = r1; r1 = r2; r2 = r3;
        }
    }
}

// S3 from S2 (vertical span 4): 8 warps, 5 rows/warp (covers 40 >= 39).
template <int SRCP, int DSTP>
__device__ __forceinline__ void build_s4_run(const float* __restrict__ src,
                                             float* __restrict__ dst,
                                             int wsub, int l, int lo, int hi) {
    const int j0 = min(2 * l, SRCP - 2);
    const bool on = (2 * l + 2 <= DSTP);
    const int i0 = lo + 5 * wsub;
    if (i0 <= hi) {                          // warp-uniform
        const float* s = src + i0 * SRCP + j0;
        float* d = dst + i0 * DSTP + 2 * l;
        #pragma unroll
        for (int k = 0; k < 5; k++) {
            float2 a = *reinterpret_cast<const float2*>(s + k * SRCP);
            float2 b = *reinterpret_cast<const float2*>(s + (k + 4) * SRCP);
            float mx = fmaxf(a.x, b.x);
            float my = fmaxf(a.y, b.y);
            float bx = __shfl_down_sync(FULLM, mx, 2);
            float by = __shfl_down_sync(FULLM, my, 2);
            if (on)
                *reinterpret_cast<float2*>(d + k * DSTP) =
                    make_float2(fmaxf(mx, bx), fmaxf(my, by));
        }
    }
}

// ---------------------------------------------------------------------------
// smem layout (floats), pad rows absorb 6-row-run overshoot:
//  sEE  @ 0     : 52 x 46 = 2392  (valid rows 0..45; writes<=50, reads<=50)
//  sS2E @ 2392  : 48 x 44 = 2112  (valid rows 0..42; writes<=47, reads<=46)
//  sS3E @ 4504  : 44 x 40 = 1760  (valid rows 0..38; writes<=42)
//  sOO  @ 6264  : 48 x 42 = 2016  (valid rows 0..41; writes<=46, reads<=46)
//  sS2O @ 8280  : 45 x 40 = 1800  (valid rows 0..38; writes<=43, reads<=42)
//  sS3O @ 10080 : 39 x 36 = 1404  (valid rows 0..34; writes<=38)
//  total 11484 floats = 45936 B -> 4 blocks/SM @ 512 thr
// ---------------------------------------------------------------------------
__global__ __launch_bounds__(512, 4) void fused_pool(const float* __restrict__ x,
                                                     float* __restrict__ out) {
    __shared__ __align__(16) float sm[11484];
    float* sEE  = sm;
    float* sS2E = sm + 2392;
    float* sS3E = sm + 4504;
    float* sOO  = sm + 6264;
    float* sS2O = sm + 8280;
    float* sS3O = sm + 10080;

    const int p   = blockIdx.z;
    const int ty0 = blockIdx.y * 32;
    const int tx0 = blockIdx.x * 32;
    const int tid = threadIdx.x;
    const int w   = tid >> 5;
    const int l   = tid & 31;

    // Column extremes of |dx| over this tile (block-uniform)
    int dxl = tx0 - 112, dxh = tx0 + 31 - 112;
    int dxmin = (dxl > 0) ? dxl : ((dxh < 0) ? -dxh : 0);
    int dxmax = max(abs(dxl), abs(dxh));
    int dxmin2 = dxmin * dxmin, dxmax2 = dxmax * dxmax;

    // Per-zone row ranges via one ballot per zone (lane = tile row)
    int l2 = 127, h2 = -1, l8 = 127, h8 = -1, l14 = 127, h14 = -1;
    int l20 = 127, h20 = -1, l26 = 127, h26 = -1;
    {
        int dy  = ty0 + l - 112;
        int rm2 = dy * dy + dxmin2;
        int rM2 = dy * dy + dxmax2;
        unsigned m;
        m = __ballot_sync(FULLM, rm2 < 3600);
        if (m) { l2  = __ffs(m) - 1; h2  = 31 - __clz(m); }
        m = __ballot_sync(FULLM, rm2 < 5625  && rM2 >= 3600);
        if (m) { l8  = __ffs(m) - 1; h8  = 31 - __clz(m); }
        m = __ballot_sync(FULLM, rm2 < 8100  && rM2 >= 5625);
        if (m) { l14 = __ffs(m) - 1; h14 = 31 - __clz(m); }
        m = __ballot_sync(FULLM, rm2 < 11025 && rM2 >= 8100);
        if (m) { l20 = __ffs(m) - 1; h20 = 31 - __clz(m); }
        m = __ballot_sync(FULLM, rM2 >= 11025);
        if (m) { l26 = __ffs(m) - 1; h26 = 31 - __clz(m); }
    }

    // Producer row ranges from consumer needs
    int s3eLo = 127, s3eHi = -1;
    if (h26 >= 0) { s3eLo = l26 + 1; s3eHi = h26 + 6; }
    int s2eLo = 127, s2eHi = -1;
    if (h14 >= 0) { s2eLo = l14 + 4; s2eHi = h14 + 7; }
    if (s3eHi >= 0) { s2eLo = min(s2eLo, s3eLo); s2eHi = max(s2eHi, s3eHi + 4); }
    s2eHi = min(s2eHi, 42);
    int eeLo = 127, eeHi = -1;
    if (h2 >= 0) { eeLo = l2 + 7; eeHi = h2 + 7; }
    if (s2eHi >= 0) { eeLo = min(eeLo, s2eLo); eeHi = max(eeHi, s2eHi + 3); }
    eeHi = min(eeHi, 45);
    s3eHi = min(s3eHi, 38);

    int s3oLo = 127, s3oHi = -1;
    if (h20 >= 0) { s3oLo = l20; s3oHi = h20 + 2; }
    int s2oLo = 127, s2oHi = -1;
    if (h8 >= 0) { s2oLo = l8 + 3; s2oHi = h8 + 3; }
    if (s3oHi >= 0) { s2oLo = min(s2oLo, s3oLo); s2oHi = max(s2oHi, s3oHi + 4); }
    s2oHi = min(s2oHi, 38);
    int ooLo = 127, ooHi = -1;
    if (s2oHi >= 0) { ooLo = s2oLo; ooHi = min(s2oHi + 3, 41); }
    s3oHi = min(s3oHi, 34);

    const float* in = x + p * (IN * IN);
    const float NEG_INF = __int_as_float(0xff800000);
    const bool xInt = (tx0 >= 32) && (tx0 <= 160);
    const bool yInt = (ty0 >= 32) && (ty0 <= 160);

    if (xInt && yInt) {
        // ==== INTERIOR FAST PATH: warp-split staging, 6 rows/warp ==========
        if (w < 8) {
            const int i0 = eeLo + 6 * w;
            if (i0 <= eeHi) {                              // warp-uniform
                const int cb = 2 * tx0 - 16 + 4 * l;       // 16B-aligned
                const float* P = in + (2 * (ty0 - 7 + i0)) * IN + cb;
                float* d = sEE + i0 * 46 + 2 * l;
                #pragma unroll
                for (int k = 0; k < 6; k++) {
                    float4 A = *reinterpret_cast<const float4*>(P + (2 * k) * IN);
                    float4 B = *reinterpret_cast<const float4*>(P + (2 * k + 1) * IN);
                    float mzw = fmax4(A.z, A.w, B.z, B.w);
                    float mxy = fmax4(A.x, A.y, B.x, B.y);
                    float v1 = __shfl_down_sync(FULLM, mxy, 1);
                    if (l < 23)
                        *reinterpret_cast<float2*>(d + k * 46) =
                            make_float2(mzw, v1);
                }
            }
        } else {
            const int i0 = ooLo + 6 * (w - 8);
            if (i0 <= ooHi) {                              // warp-uniform
                const int cb = 2 * tx0 - 12 + 4 * l;       // 16B-aligned
                const float* P = in + (2 * (ty0 - 5 + i0) + 1) * IN + cb;
                float* d = sOO + i0 * 42 + 2 * l;
                #pragma unroll
                for (int k = 0; k < 6; k++) {
                    float4 A = *reinterpret_cast<const float4*>(P + (2 * k) * IN);
                    float4 B = *reinterpret_cast<const float4*>(P + (2 * k + 1) * IN);
                    float mw  = fmaxf(A.w, B.w);
                    float mx  = fmaxf(A.x, B.x);
                    float dyz = fmax4(A.y, A.z, B.y, B.z);
                    float nx = __shfl_down_sync(FULLM, mx, 1);
                    float nd = __shfl_down_sync(FULLM, dyz, 1);
                    if (l < 21)
                        *reinterpret_cast<float2*>(d + k * 42) =
                            make_float2(fmaxf(mw, nx), nd);
                }
            }
        }
    } else {
        // ================= GENERAL PATH (border tiles) =====================
        if (xInt) {
            const int cb = 2 * tx0 - 16 + 4 * l;
            for (int i = eeLo + w; i <= eeHi; i += 16) {
                int yp = ty0 - 7 + i;
                int r0, r1;
                if ((unsigned)yp < 224u) { r0 = 2 * yp; r1 = 2 * yp + 1; }
                else                     { r0 = refl(2 * yp); r1 = refl(2 * yp + 1); }
                float4 A = *reinterpret_cast<const float4*>(in + r0 * IN + cb);
                float4 B = *reinterpret_cast<const float4*>(in + r1 * IN + cb);
                float mzw = fmax4(A.z, A.w, B.z, B.w);
                float mxy = fmax4(A.x, A.y, B.x, B.y);
                float v1 = __shfl_down_sync(FULLM, mxy, 1);
                if (l < 23)
                    *reinterpret_cast<float2*>(sEE + i * 46 + 2 * l) =
                        make_float2(mzw, v1);
            }
        } else if (l < 23) {
            const int j0 = 2 * l;
            for (int i = eeLo + w; i <= eeHi; i += 16) {
                int yp = ty0 - 7 + i;
                int r0, r1;
                if ((unsigned)yp < 224u) { r0 = 2 * yp; r1 = 2 * yp + 1; }
                else                     { r0 = refl(2 * yp); r1 = refl(2 * yp + 1); }
                const float* R0 = in + r0 * IN;
                const float* R1 = in + r1 * IN;
                int xp0 = tx0 - 7 + j0;
                float v0, v1;
                if ((unsigned)xp0 < 223u) {
                    float2 a = *reinterpret_cast<const float2*>(R0 + 2 * xp0);
                    float2 b = *reinterpret_cast<const float2*>(R0 + 2 * xp0 + 2);
                    float2 c = *reinterpret_cast<const float2*>(R1 + 2 * xp0);
                    float2 d = *reinterpret_cast<const float2*>(R1 + 2 * xp0 + 2);
                    v0 = fmax4(a.x, a.y, c.x, c.y);
                    v1 = fmax4(b.x, b.y, d.x, d.y);
                } else {
                    int c0 = refl(2 * xp0),     c1 = refl(2 * xp0 + 1);
                    v0 = fmax4(R0[c0], R0[c1], R1[c0], R1[c1]);
                    int c2 = refl(2 * xp0 + 2), c3 = refl(2 * xp0 + 3);
                    v1 = fmax4(R0[c2], R0[c3], R1[c2], R1[c3]);
                }
                *reinterpret_cast<float2*>(sEE + i * 46 + j0) = make_float2(v0, v1);
            }
        }

        if (xInt) {
            const int cb = 2 * tx0 - 12 + 4 * l;
            for (int i = ooLo + w; i <= ooHi; i += 16) {
                int gy = ty0 - 5 + i;
                float v0 = NEG_INF, v1 = NEG_INF;
                if ((unsigned)gy < 224u) {        // warp-uniform
                    int r0 = 2 * gy + 1;
                    int r1 = (gy == 223) ? 446 : 2 * gy + 2;
                    float4 A = *reinterpret_cast<const float4*>(in + r0 * IN + cb);
                    float4 B = *reinterpret_cast<const float4*>(in + r1 * IN + cb);
                    float mw  = fmaxf(A.w, B.w);
                    float mx  = fmaxf(A.x, B.x);
                    float dyz = fmax4(A.y, A.z, B.y, B.z);
                    float nx = __shfl_down_sync(FULLM, mx, 1);
                    float nd = __shfl_down_sync(FULLM, dyz, 1);
                    v0 = fmaxf(mw, nx);
                    v1 = nd;
                }
                if (l < 21)
                    *reinterpret_cast<float2*>(sOO + i * 42 + 2 * l) =
                        make_float2(v0, v1);
            }
        } else if (l < 21) {
            const int j0 = 2 * l;
            for (int i = ooLo + w; i <= ooHi; i += 16) {
                int gy = ty0 - 5 + i;
                float v0 = NEG_INF, v1 = NEG_INF;
                if ((unsigned)gy < 224u) {
                    int r0 = 2 * gy + 1;
                    int r1 = (gy == 223) ? 446 : 2 * gy + 2;
                    const float* R0 = in + r0 * IN;
                    const float* R1 = in + r1 * IN;
                    int gx0 = tx0 - 5 + j0;
                    if ((unsigned)gx0 < 224u) {
                        int c0 = 2 * gx0 + 1;
                        int c1 = (gx0 == 223) ? 446 : 2 * gx0 + 2;
                        v0 = fmax4(R0[c0], R0[c1], R1[c0], R1[c1]);
                    }
                    int gx1 = gx0 + 1;
                    if ((unsigned)gx1 < 224u) {
                        int c0 = 2 * gx1 + 1;
                        int c1 = (gx1 == 223) ? 446 : 2 * gx1 + 2;
                        v1 = fmax4(R0[c0], R0[c1], R1[c0], R1[c1]);
                    }
                }
                *reinterpret_cast<float2*>(sOO + i * 42 + j0) = make_float2(v0, v1);
            }
        }
    }
    __syncthreads();

    // ---- Level-2 tables (4x4 windows): E on warps 0-7, O on warps 8-15
    if (w < 8) build_s2_run<46, 44>(sEE, sS2E, w,     l, s2eLo, s2eHi);
    else       build_s2_run<42, 40>(sOO, sS2O, w - 8, l, s2oLo, s2oHi);
    __syncthreads();

    // ---- Level-3 tables (8x8 windows): same split
    if (w < 8) build_s4_run<44, 40>(sS2E, sS3E, w,     l, s3eLo, s3eHi);
    else       build_s4_run<40, 36>(sS2O, sS3O, w - 8, l, s3oLo, s3oHi);
    __syncthreads();

    // ---- Queries: 2 output pixels per thread
    #pragma unroll
    for (int q = 0; q < 2; q++) {
        int ry = w + q * 16;
        int rx = l;
        int oy = ty0 + ry, ox = tx0 + rx;
        int dy = oy - 112, dx = ox - 112;
        int d2 = dy * dy + dx * dx;
        float v;
        if (d2 < 3600) {
            v = sEE[(ry + 7) * 46 + (rx + 7)];                       // k=2
        } else if (d2 < 5625) {
            v = sS2O[(ry + 3) * 40 + (rx + 3)];                      // k=8
        } else if (d2 < 8100) {
            const float* b = sS2E + (ry + 4) * 44 + (rx + 4);        // k=14
            v = fmax4(b[0], b[3], b[3 * 44], b[3 * 44 + 3]);
        } else if (d2 < 11025) {
            const float* b = sS3O + ry * 36 + rx;                    // k=20
            v = fmax4(b[0], b[2], b[2 * 36], b[2 * 36 + 2]);
        } else {
            const float* b = sS3E + (ry + 1) * 40 + (rx + 1);        // k=26
            v = fmax4(b[0], b[5], b[5 * 40], b[5 * 40 + 5]);
        }
        out[(p * OUT + oy) * OUT + ox] = v;
    }
}

extern "C" void kernel_launch(void* const* d_in, const int* in_sizes, int n_in,
                              void* d_out, int out_size) {
    const float* x = (const float*)d_in[0];
    float* out = (float*)d_out;
    fused_pool<<<dim3(7, 7, NP), 512>>>(x, out);
}